// round 5
// baseline (speedup 1.0000x reference)
#include <cuda_runtime.h>
#include <cstdint>

// ResRnn persistent kernel, 128 CTAs x 512 threads.
// R4: packed f32x2 FMA (FFMA2) — row-pairs packed in 64-bit, s broadcast-packed.
//     Explicit double-buffered prefetch of state loads (MLP=8).

#define SEQ   1024
#define BATCH 256
#define INSZ  64
#define SSZ   1024
#define OUTSZ 64
#define NCTA  128
#define RPC   8
#define NTHR  512
#define HALF  (SSZ / 2)
#define UNR   8

__device__ float g_S[2][SSZ][BATCH];   // double-buffered shifted stream, [k][b]
__device__ float g_H[SSZ][BATCH];      // hidden activations, [i][b]
__device__ unsigned g_ctr;
__device__ volatile unsigned g_epoch;

#define FMA2(d, a, b) asm("fma.rn.f32x2 %0, %1, %2, %0;" : "+l"(d) : "l"(a), "l"(b))
#define PACK2(d, f)   asm("mov.b64 %0, {%1, %1};" : "=l"(d) : "f"(f))
#define UNPACK2(lo, hi, v) asm("mov.b64 {%0, %1}, %2;" : "=f"(lo), "=f"(hi) : "l"(v))

__device__ __forceinline__ void gbar(unsigned ep0, unsigned idx) {
    __syncthreads();
    if (threadIdx.x == 0) {
        __threadfence();
        unsigned old = atomicAdd(&g_ctr, 1u);
        if (old == NCTA - 1u) {
            g_ctr = 0u;
            __threadfence();
            atomicAdd((unsigned*)&g_epoch, 1u);
        } else {
            while ((unsigned)(g_epoch - ep0) < idx) { }
        }
        __threadfence();
    }
    __syncthreads();
}

// Dot of a K-half against 8 W rows (packed as 4 f32x2 pairs), src in gmem [k][BATCH].
__device__ __forceinline__ void dot_half(const float* __restrict__ src,
                                         const ulonglong2* __restrict__ wp,
                                         unsigned long long acc[4])
{
    float cur[UNR], nxt[UNR];
#pragma unroll
    for (int u = 0; u < UNR; ++u) nxt[u] = src[(size_t)u * BATCH];

#pragma unroll 1
    for (int kk = 0; kk < HALF - UNR; kk += UNR) {
#pragma unroll
        for (int u = 0; u < UNR; ++u) cur[u] = nxt[u];
#pragma unroll
        for (int u = 0; u < UNR; ++u) nxt[u] = src[(size_t)(kk + UNR + u) * BATCH];
#pragma unroll
        for (int u = 0; u < UNR; ++u) {
            unsigned long long s2; PACK2(s2, cur[u]);
            ulonglong2 wa = wp[2 * (kk + u)];
            ulonglong2 wb = wp[2 * (kk + u) + 1];
            FMA2(acc[0], wa.x, s2);
            FMA2(acc[1], wa.y, s2);
            FMA2(acc[2], wb.x, s2);
            FMA2(acc[3], wb.y, s2);
        }
    }
    // final chunk
#pragma unroll
    for (int u = 0; u < UNR; ++u) {
        const int k = HALF - UNR + u;
        unsigned long long s2; PACK2(s2, nxt[u]);
        ulonglong2 wa = wp[2 * k];
        ulonglong2 wb = wp[2 * k + 1];
        FMA2(acc[0], wa.x, s2);
        FMA2(acc[1], wa.y, s2);
        FMA2(acc[2], wb.x, s2);
        FMA2(acc[3], wb.y, s2);
    }
}

__global__ __launch_bounds__(NTHR, 1)
void resrnn_kernel(const float* __restrict__ x,
                   const float* __restrict__ W1,
                   const float* __restrict__ b1,
                   const float* __restrict__ W2,
                   const float* __restrict__ b2,
                   float* __restrict__ out)
{
    extern __shared__ float smem[];
    float* W1sT = smem;                        // [SSZ][RPC] (transposed)
    float* W2sT = smem + SSZ * RPC;            // [SSZ][RPC]
    float* red  = smem + 2 * SSZ * RPC;        // [BATCH][9] partials (odd pad)
    float* b1s  = red + BATCH * 9;
    float* b2s  = b1s + RPC;

    const int tid = threadIdx.x;
    const int cta = blockIdx.x;
    const int i0  = cta * RPC;

    const unsigned ep0 = g_epoch;

    for (int idx = tid; idx < RPC * SSZ; idx += NTHR) {
        int r = idx >> 10, k = idx & (SSZ - 1);
        W1sT[k * RPC + r] = W1[(size_t)(i0 + r) * SSZ + k];
        W2sT[k * RPC + r] = W2[(size_t)(i0 + r) * SSZ + k];
    }
    if (tid < RPC) { b1s[tid] = b1[i0 + tid]; b2s[tid] = b2[i0 + tid]; }

    for (int idx = tid; idx < RPC * BATCH; idx += NTHR) {
        int r = idx >> 8, b = idx & (BATCH - 1);
        int kk = i0 + r;
        g_S[0][kk][b] = (kk < INSZ) ? x[(size_t)b * INSZ + kk] : 0.0f;
    }

    unsigned bc = 0;
    gbar(ep0, ++bc);

    const int wid  = tid >> 5, lane = tid & 31;
    const int wg   = wid >> 3;                 // K-half 0/1
    const int w8   = wid & 7;
    const int b    = w8 * 32 + lane;           // batch index (coalesced)
    const int k0   = wg * HALF;

    const ulonglong2* w1p = (const ulonglong2*)(W1sT + k0 * RPC);
    const ulonglong2* w2p = (const ulonglong2*)(W2sT + k0 * RPC);

    const float p = 0.97f;
    const float q = 1.0f - 0.97f;

    for (int t = 0; t < SEQ; ++t) {
        const float* __restrict__ Scur = &g_S[t & 1][0][0];
        float*       __restrict__ Snxt = &g_S[(t + 1) & 1][0][0];

        // ------- Phase 1: H[i0+r][b] = |dot(s, W1 row) + b1| -------
        {
            unsigned long long acc[4] = {0ull, 0ull, 0ull, 0ull};
            dot_half(Scur + (size_t)k0 * BATCH + b, w1p, acc);

            float a[RPC];
            UNPACK2(a[0], a[1], acc[0]);
            UNPACK2(a[2], a[3], acc[1]);
            UNPACK2(a[4], a[5], acc[2]);
            UNPACK2(a[6], a[7], acc[3]);

            if (wg == 1) {
#pragma unroll
                for (int r = 0; r < RPC; ++r) red[b * 9 + r] = a[r];
            }
            __syncthreads();
            if (wg == 0) {
#pragma unroll
                for (int r = 0; r < RPC; ++r)
                    g_H[i0 + r][b] = fabsf(a[r] + red[b * 9 + r] + b1s[r]);
            }
        }
        gbar(ep0, ++bc);

        // ------- Phase 2: s_new = p*s + q*(dot(h, W2 row) + b2) -------
        {
            unsigned long long acc[4] = {0ull, 0ull, 0ull, 0ull};
            dot_half(&g_H[0][0] + (size_t)k0 * BATCH + b, w2p, acc);

            float a[RPC];
            UNPACK2(a[0], a[1], acc[0]);
            UNPACK2(a[2], a[3], acc[1]);
            UNPACK2(a[4], a[5], acc[2]);
            UNPACK2(a[6], a[7], acc[3]);

            if (wg == 1) {
#pragma unroll
                for (int r = 0; r < RPC; ++r) red[b * 9 + r] = a[r];
            }
            __syncthreads();
            if (wg == 0) {
#pragma unroll
                for (int r = 0; r < RPC; ++r) {
                    int j = i0 + r;
                    float snew = p * Scur[(size_t)j * BATCH + b]
                               + q * (a[r] + red[b * 9 + r] + b2s[r]);
                    if (j < SSZ - INSZ)
                        Snxt[(size_t)(j + INSZ) * BATCH + b] = snew;
                    if (t == SEQ - 1 && j >= SSZ - OUTSZ)
                        out[b * OUTSZ + (j - (SSZ - OUTSZ))] = snew;
                }
            }
            if (i0 < INSZ && t + 1 < SEQ && wg == 1) {
#pragma unroll
                for (int r = 0; r < RPC; ++r) {
                    int kk = i0 + r;
                    Snxt[(size_t)kk * BATCH + b] =
                        x[(size_t)(t + 1) * BATCH * INSZ + (size_t)b * INSZ + kk];
                }
            }
        }
        gbar(ep0, ++bc);
    }
}

extern "C" void kernel_launch(void* const* d_in, const int* in_sizes, int n_in,
                              void* d_out, int out_size) {
    (void)in_sizes; (void)n_in; (void)out_size;
    const float* x  = (const float*)d_in[0];
    const float* W1 = (const float*)d_in[1];
    const float* b1 = (const float*)d_in[2];
    const float* W2 = (const float*)d_in[3];
    const float* b2 = (const float*)d_in[4];

    const size_t smem_bytes =
        (size_t)(2 * SSZ * RPC + BATCH * 9 + 2 * RPC) * sizeof(float);
    cudaFuncSetAttribute(resrnn_kernel,
                         cudaFuncAttributeMaxDynamicSharedMemorySize,
                         (int)smem_bytes);
    resrnn_kernel<<<NCTA, NTHR, smem_bytes>>>(x, W1, b1, W2, b2, (float*)d_out);
}

// round 6
// speedup vs baseline: 1.0015x; 1.0015x over previous
#include <cuda_runtime.h>
#include <cstdint>

// ResRnn persistent kernel, 128 CTAs x 512 threads.
// R4: packed f32x2 FMA (FFMA2) — row-pairs packed in 64-bit, s broadcast-packed.
//     Explicit double-buffered prefetch of state loads (MLP=8).

#define SEQ   1024
#define BATCH 256
#define INSZ  64
#define SSZ   1024
#define OUTSZ 64
#define NCTA  128
#define RPC   8
#define NTHR  512
#define HALF  (SSZ / 2)
#define UNR   8

__device__ float g_S[2][SSZ][BATCH];   // double-buffered shifted stream, [k][b]
__device__ float g_H[SSZ][BATCH];      // hidden activations, [i][b]
__device__ unsigned g_ctr;
__device__ volatile unsigned g_epoch;

#define FMA2(d, a, b) asm("fma.rn.f32x2 %0, %1, %2, %0;" : "+l"(d) : "l"(a), "l"(b))
#define PACK2(d, f)   asm("mov.b64 %0, {%1, %1};" : "=l"(d) : "f"(f))
#define UNPACK2(lo, hi, v) asm("mov.b64 {%0, %1}, %2;" : "=f"(lo), "=f"(hi) : "l"(v))

__device__ __forceinline__ void gbar(unsigned ep0, unsigned idx) {
    __syncthreads();
    if (threadIdx.x == 0) {
        __threadfence();
        unsigned old = atomicAdd(&g_ctr, 1u);
        if (old == NCTA - 1u) {
            g_ctr = 0u;
            __threadfence();
            atomicAdd((unsigned*)&g_epoch, 1u);
        } else {
            while ((unsigned)(g_epoch - ep0) < idx) { }
        }
        __threadfence();
    }
    __syncthreads();
}

// Dot of a K-half against 8 W rows (packed as 4 f32x2 pairs), src in gmem [k][BATCH].
__device__ __forceinline__ void dot_half(const float* __restrict__ src,
                                         const ulonglong2* __restrict__ wp,
                                         unsigned long long acc[4])
{
    float cur[UNR], nxt[UNR];
#pragma unroll
    for (int u = 0; u < UNR; ++u) nxt[u] = src[(size_t)u * BATCH];

#pragma unroll 1
    for (int kk = 0; kk < HALF - UNR; kk += UNR) {
#pragma unroll
        for (int u = 0; u < UNR; ++u) cur[u] = nxt[u];
#pragma unroll
        for (int u = 0; u < UNR; ++u) nxt[u] = src[(size_t)(kk + UNR + u) * BATCH];
#pragma unroll
        for (int u = 0; u < UNR; ++u) {
            unsigned long long s2; PACK2(s2, cur[u]);
            ulonglong2 wa = wp[2 * (kk + u)];
            ulonglong2 wb = wp[2 * (kk + u) + 1];
            FMA2(acc[0], wa.x, s2);
            FMA2(acc[1], wa.y, s2);
            FMA2(acc[2], wb.x, s2);
            FMA2(acc[3], wb.y, s2);
        }
    }
    // final chunk
#pragma unroll
    for (int u = 0; u < UNR; ++u) {
        const int k = HALF - UNR + u;
        unsigned long long s2; PACK2(s2, nxt[u]);
        ulonglong2 wa = wp[2 * k];
        ulonglong2 wb = wp[2 * k + 1];
        FMA2(acc[0], wa.x, s2);
        FMA2(acc[1], wa.y, s2);
        FMA2(acc[2], wb.x, s2);
        FMA2(acc[3], wb.y, s2);
    }
}

__global__ __launch_bounds__(NTHR, 1)
void resrnn_kernel(const float* __restrict__ x,
                   const float* __restrict__ W1,
                   const float* __restrict__ b1,
                   const float* __restrict__ W2,
                   const float* __restrict__ b2,
                   float* __restrict__ out)
{
    extern __shared__ float smem[];
    float* W1sT = smem;                        // [SSZ][RPC] (transposed)
    float* W2sT = smem + SSZ * RPC;            // [SSZ][RPC]
    float* red  = smem + 2 * SSZ * RPC;        // [BATCH][9] partials (odd pad)
    float* b1s  = red + BATCH * 9;
    float* b2s  = b1s + RPC;

    const int tid = threadIdx.x;
    const int cta = blockIdx.x;
    const int i0  = cta * RPC;

    const unsigned ep0 = g_epoch;

    for (int idx = tid; idx < RPC * SSZ; idx += NTHR) {
        int r = idx >> 10, k = idx & (SSZ - 1);
        W1sT[k * RPC + r] = W1[(size_t)(i0 + r) * SSZ + k];
        W2sT[k * RPC + r] = W2[(size_t)(i0 + r) * SSZ + k];
    }
    if (tid < RPC) { b1s[tid] = b1[i0 + tid]; b2s[tid] = b2[i0 + tid]; }

    for (int idx = tid; idx < RPC * BATCH; idx += NTHR) {
        int r = idx >> 8, b = idx & (BATCH - 1);
        int kk = i0 + r;
        g_S[0][kk][b] = (kk < INSZ) ? x[(size_t)b * INSZ + kk] : 0.0f;
    }

    unsigned bc = 0;
    gbar(ep0, ++bc);

    const int wid  = tid >> 5, lane = tid & 31;
    const int wg   = wid >> 3;                 // K-half 0/1
    const int w8   = wid & 7;
    const int b    = w8 * 32 + lane;           // batch index (coalesced)
    const int k0   = wg * HALF;

    const ulonglong2* w1p = (const ulonglong2*)(W1sT + k0 * RPC);
    const ulonglong2* w2p = (const ulonglong2*)(W2sT + k0 * RPC);

    const float p = 0.97f;
    const float q = 1.0f - 0.97f;

    for (int t = 0; t < SEQ; ++t) {
        const float* __restrict__ Scur = &g_S[t & 1][0][0];
        float*       __restrict__ Snxt = &g_S[(t + 1) & 1][0][0];

        // ------- Phase 1: H[i0+r][b] = |dot(s, W1 row) + b1| -------
        {
            unsigned long long acc[4] = {0ull, 0ull, 0ull, 0ull};
            dot_half(Scur + (size_t)k0 * BATCH + b, w1p, acc);

            float a[RPC];
            UNPACK2(a[0], a[1], acc[0]);
            UNPACK2(a[2], a[3], acc[1]);
            UNPACK2(a[4], a[5], acc[2]);
            UNPACK2(a[6], a[7], acc[3]);

            if (wg == 1) {
#pragma unroll
                for (int r = 0; r < RPC; ++r) red[b * 9 + r] = a[r];
            }
            __syncthreads();
            if (wg == 0) {
#pragma unroll
                for (int r = 0; r < RPC; ++r)
                    g_H[i0 + r][b] = fabsf(a[r] + red[b * 9 + r] + b1s[r]);
            }
        }
        gbar(ep0, ++bc);

        // ------- Phase 2: s_new = p*s + q*(dot(h, W2 row) + b2) -------
        {
            unsigned long long acc[4] = {0ull, 0ull, 0ull, 0ull};
            dot_half(&g_H[0][0] + (size_t)k0 * BATCH + b, w2p, acc);

            float a[RPC];
            UNPACK2(a[0], a[1], acc[0]);
            UNPACK2(a[2], a[3], acc[1]);
            UNPACK2(a[4], a[5], acc[2]);
            UNPACK2(a[6], a[7], acc[3]);

            if (wg == 1) {
#pragma unroll
                for (int r = 0; r < RPC; ++r) red[b * 9 + r] = a[r];
            }
            __syncthreads();
            if (wg == 0) {
#pragma unroll
                for (int r = 0; r < RPC; ++r) {
                    int j = i0 + r;
                    float snew = p * Scur[(size_t)j * BATCH + b]
                               + q * (a[r] + red[b * 9 + r] + b2s[r]);
                    if (j < SSZ - INSZ)
                        Snxt[(size_t)(j + INSZ) * BATCH + b] = snew;
                    if (t == SEQ - 1 && j >= SSZ - OUTSZ)
                        out[b * OUTSZ + (j - (SSZ - OUTSZ))] = snew;
                }
            }
            if (i0 < INSZ && t + 1 < SEQ && wg == 1) {
#pragma unroll
                for (int r = 0; r < RPC; ++r) {
                    int kk = i0 + r;
                    Snxt[(size_t)kk * BATCH + b] =
                        x[(size_t)(t + 1) * BATCH * INSZ + (size_t)b * INSZ + kk];
                }
            }
        }
        gbar(ep0, ++bc);
    }
}

extern "C" void kernel_launch(void* const* d_in, const int* in_sizes, int n_in,
                              void* d_out, int out_size) {
    (void)in_sizes; (void)n_in; (void)out_size;
    const float* x  = (const float*)d_in[0];
    const float* W1 = (const float*)d_in[1];
    const float* b1 = (const float*)d_in[2];
    const float* W2 = (const float*)d_in[3];
    const float* b2 = (const float*)d_in[4];

    const size_t smem_bytes =
        (size_t)(2 * SSZ * RPC + BATCH * 9 + 2 * RPC) * sizeof(float);
    cudaFuncSetAttribute(resrnn_kernel,
                         cudaFuncAttributeMaxDynamicSharedMemorySize,
                         (int)smem_bytes);
    resrnn_kernel<<<NCTA, NTHR, smem_bytes>>>(x, W1, b1, W2, b2, (float*)d_out);
}

// round 7
// speedup vs baseline: 1.6263x; 1.6239x over previous
#include <cuda_runtime.h>
#include <cstdint>

// ResRnn persistent kernel. R6: 128 CTAs x 1024 threads (occ 50%).
// 32 warps = 8 K-eighths x 4 batch-warps; each thread covers 2 adjacent
// batches (LDG.64 state, packed f32x2 FMA on 8 W rows). SMEM partial tree
// combines the 8 K-splits.

#define SEQ   1024
#define BATCH 256
#define INSZ  64
#define SSZ   1024
#define OUTSZ 64
#define NCTA  128
#define RPC   8
#define NTHR  1024
#define KSPL  8
#define KSEG  (SSZ / KSPL)      // 128
#define UNR   4

__device__ float g_S[2][SSZ][BATCH];
__device__ float g_H[SSZ][BATCH];
__device__ unsigned g_ctr;
__device__ volatile unsigned g_epoch;

#define FMA2(d, a, b) asm("fma.rn.f32x2 %0, %1, %2, %0;" : "+l"(d) : "l"(a), "l"(b))
#define PACK2(d, f)   asm("mov.b64 %0, {%1, %1};" : "=l"(d) : "f"(f))
#define UNPACK2(lo, hi, v) asm("mov.b64 {%0, %1}, %2;" : "=f"(lo), "=f"(hi) : "l"(v))

__device__ __forceinline__ void gbar(unsigned ep0, unsigned idx) {
    __syncthreads();
    if (threadIdx.x == 0) {
        __threadfence();
        unsigned old = atomicAdd(&g_ctr, 1u);
        if (old == NCTA - 1u) {
            g_ctr = 0u;
            __threadfence();
            atomicAdd((unsigned*)&g_epoch, 1u);
        } else {
            while ((unsigned)(g_epoch - ep0) < idx) { }
        }
        __threadfence();
    }
    __syncthreads();
}

// K-segment dot: 2 batches x 8 rows. src_f2 points at [k][b0/2] float2,
// stride BATCH/2 float2 per k. Accumulators: a0 (batch b0) and a1 (b0+1),
// each 4 x f32x2 covering 8 rows.
__device__ __forceinline__ void dot_seg(const float2* __restrict__ src,
                                        const ulonglong2* __restrict__ wp,
                                        unsigned long long a0[4],
                                        unsigned long long a1[4])
{
    float2 cur[UNR], nxt[UNR];
#pragma unroll
    for (int u = 0; u < UNR; ++u) nxt[u] = src[(size_t)u * (BATCH / 2)];

#pragma unroll 1
    for (int kk = 0; kk < KSEG - UNR; kk += UNR) {
#pragma unroll
        for (int u = 0; u < UNR; ++u) cur[u] = nxt[u];
#pragma unroll
        for (int u = 0; u < UNR; ++u)
            nxt[u] = src[(size_t)(kk + UNR + u) * (BATCH / 2)];
#pragma unroll
        for (int u = 0; u < UNR; ++u) {
            unsigned long long s0, s1;
            PACK2(s0, cur[u].x);
            PACK2(s1, cur[u].y);
            ulonglong2 wa = wp[2 * (kk + u)];
            ulonglong2 wb = wp[2 * (kk + u) + 1];
            FMA2(a0[0], wa.x, s0); FMA2(a0[1], wa.y, s0);
            FMA2(a0[2], wb.x, s0); FMA2(a0[3], wb.y, s0);
            FMA2(a1[0], wa.x, s1); FMA2(a1[1], wa.y, s1);
            FMA2(a1[2], wb.x, s1); FMA2(a1[3], wb.y, s1);
        }
    }
#pragma unroll
    for (int u = 0; u < UNR; ++u) {
        const int k = KSEG - UNR + u;
        unsigned long long s0, s1;
        PACK2(s0, nxt[u].x);
        PACK2(s1, nxt[u].y);
        ulonglong2 wa = wp[2 * k];
        ulonglong2 wb = wp[2 * k + 1];
        FMA2(a0[0], wa.x, s0); FMA2(a0[1], wa.y, s0);
        FMA2(a0[2], wb.x, s0); FMA2(a0[3], wb.y, s0);
        FMA2(a1[0], wa.x, s1); FMA2(a1[1], wa.y, s1);
        FMA2(a1[2], wb.x, s1); FMA2(a1[3], wb.y, s1);
    }
}

__device__ __forceinline__ void unpack8(const unsigned long long a[4], float o[8]) {
    UNPACK2(o[0], o[1], a[0]);
    UNPACK2(o[2], o[3], a[1]);
    UNPACK2(o[4], o[5], a[2]);
    UNPACK2(o[6], o[7], a[3]);
}

__global__ __launch_bounds__(NTHR, 1)
void resrnn_kernel(const float* __restrict__ x,
                   const float* __restrict__ W1,
                   const float* __restrict__ b1,
                   const float* __restrict__ W2,
                   const float* __restrict__ b2,
                   float* __restrict__ out)
{
    extern __shared__ float smem[];
    float* W1sT = smem;                          // [SSZ][RPC] transposed
    float* W2sT = smem + SSZ * RPC;              // [SSZ][RPC]
    float* red  = smem + 2 * SSZ * RPC;          // [KSPL-1][BATCH][9]
    float* b1s  = red + (KSPL - 1) * BATCH * 9;  // [RPC]
    float* b2s  = b1s + RPC;                     // [RPC]

    const int tid = threadIdx.x;
    const int cta = blockIdx.x;
    const int i0  = cta * RPC;

    const unsigned ep0 = g_epoch;

    for (int idx = tid; idx < RPC * SSZ; idx += NTHR) {
        int k = idx >> 3, r = idx & 7;
        W1sT[idx] = W1[(size_t)(i0 + r) * SSZ + k];
        W2sT[idx] = W2[(size_t)(i0 + r) * SSZ + k];
    }
    if (tid < RPC) { b1s[tid] = b1[i0 + tid]; b2s[tid] = b2[i0 + tid]; }

    for (int idx = tid; idx < RPC * BATCH; idx += NTHR) {
        int r = idx >> 8, b = idx & (BATCH - 1);
        int kk = i0 + r;
        g_S[0][kk][b] = (kk < INSZ) ? x[(size_t)b * INSZ + kk] : 0.0f;
    }

    unsigned bc = 0;
    gbar(ep0, ++bc);

    const int wid  = tid >> 5, lane = tid & 31;
    const int kq   = wid >> 2;                  // K-eighth 0..7
    const int bw   = wid & 3;                   // batch warp 0..3
    const int b0   = bw * 64 + lane * 2;        // 2 adjacent batches
    const int k0   = kq * KSEG;

    const ulonglong2* w1p = (const ulonglong2*)(W1sT + k0 * RPC);
    const ulonglong2* w2p = (const ulonglong2*)(W2sT + k0 * RPC);
    float* red0 = (kq > 0) ? (red + ((kq - 1) * BATCH + b0) * 9) : nullptr;
    float* red1 = (kq > 0) ? (red0 + 9) : nullptr;

    const float p = 0.97f;
    const float q = 1.0f - 0.97f;

    for (int t = 0; t < SEQ; ++t) {
        const float* __restrict__ Scur = &g_S[t & 1][0][0];
        float*       __restrict__ Snxt = &g_S[(t + 1) & 1][0][0];

        // -------- Phase 1: H[i0+r][b] = |dot(s, W1 row) + b1| --------
        {
            unsigned long long a0[4] = {0,0,0,0}, a1[4] = {0,0,0,0};
            dot_seg((const float2*)(Scur + (size_t)k0 * BATCH) + (b0 >> 1),
                    w1p, a0, a1);
            float v0[8], v1[8];
            unpack8(a0, v0); unpack8(a1, v1);
            if (kq > 0) {
#pragma unroll
                for (int r = 0; r < RPC; ++r) { red0[r] = v0[r]; red1[r] = v1[r]; }
            }
            __syncthreads();
            if (kq == 0) {
#pragma unroll
                for (int r = 0; r < RPC; ++r) {
                    float s0 = v0[r], s1 = v1[r];
#pragma unroll
                    for (int qx = 1; qx < KSPL; ++qx) {
                        s0 += red[((qx - 1) * BATCH + b0) * 9 + r];
                        s1 += red[((qx - 1) * BATCH + b0 + 1) * 9 + r];
                    }
                    float2 hv = make_float2(fabsf(s0 + b1s[r]), fabsf(s1 + b1s[r]));
                    *(float2*)&g_H[i0 + r][b0] = hv;
                }
            }
        }
        gbar(ep0, ++bc);

        // -------- Phase 2: s_new = p*s + q*(dot(h, W2 row) + b2) --------
        {
            unsigned long long a0[4] = {0,0,0,0}, a1[4] = {0,0,0,0};
            dot_seg((const float2*)(&g_H[0][0] + (size_t)k0 * BATCH) + (b0 >> 1),
                    w2p, a0, a1);
            float v0[8], v1[8];
            unpack8(a0, v0); unpack8(a1, v1);
            if (kq > 0) {
#pragma unroll
                for (int r = 0; r < RPC; ++r) { red0[r] = v0[r]; red1[r] = v1[r]; }
            }
            __syncthreads();
            if (kq == 0) {
#pragma unroll
                for (int r = 0; r < RPC; ++r) {
                    float s0 = v0[r], s1 = v1[r];
#pragma unroll
                    for (int qx = 1; qx < KSPL; ++qx) {
                        s0 += red[((qx - 1) * BATCH + b0) * 9 + r];
                        s1 += red[((qx - 1) * BATCH + b0 + 1) * 9 + r];
                    }
                    int j = i0 + r;
                    float2 sold = *(const float2*)&Scur[(size_t)j * BATCH + b0];
                    float n0 = p * sold.x + q * (s0 + b2s[r]);
                    float n1 = p * sold.y + q * (s1 + b2s[r]);
                    if (j < SSZ - INSZ)
                        *(float2*)&Snxt[(size_t)(j + INSZ) * BATCH + b0] =
                            make_float2(n0, n1);
                    if (t == SEQ - 1 && j >= SSZ - OUTSZ) {
                        int jo = j - (SSZ - OUTSZ);
                        out[b0 * OUTSZ + jo]       = n0;
                        out[(b0 + 1) * OUTSZ + jo] = n1;
                    }
                }
            }
            // inject x_{t+1} into rows [0,64) of next buffer (kq==1 warps)
            if (i0 < INSZ && t + 1 < SEQ && kq == 1) {
                const float* xp = x + (size_t)(t + 1) * BATCH * INSZ;
#pragma unroll
                for (int r = 0; r < RPC; ++r) {
                    int kk = i0 + r;
                    float2 xv = make_float2(xp[(size_t)b0 * INSZ + kk],
                                            xp[(size_t)(b0 + 1) * INSZ + kk]);
                    *(float2*)&Snxt[(size_t)kk * BATCH + b0] = xv;
                }
            }
        }
        gbar(ep0, ++bc);
    }
}

extern "C" void kernel_launch(void* const* d_in, const int* in_sizes, int n_in,
                              void* d_out, int out_size) {
    (void)in_sizes; (void)n_in; (void)out_size;
    const float* x  = (const float*)d_in[0];
    const float* W1 = (const float*)d_in[1];
    const float* b1 = (const float*)d_in[2];
    const float* W2 = (const float*)d_in[3];
    const float* b2 = (const float*)d_in[4];

    const size_t smem_bytes =
        (size_t)(2 * SSZ * RPC + (KSPL - 1) * BATCH * 9 + 2 * RPC) * sizeof(float);
    cudaFuncSetAttribute(resrnn_kernel,
                         cudaFuncAttributeMaxDynamicSharedMemorySize,
                         (int)smem_bytes);
    resrnn_kernel<<<NCTA, NTHR, smem_bytes>>>(x, W1, b1, W2, b2, (float*)d_out);
}

// round 9
// speedup vs baseline: 1.7329x; 1.0655x over previous
#include <cuda_runtime.h>
#include <cuda_bf16.h>
#include <cstdint>

// ResRnn via warp-level bf16 tensor cores (mma.sync.m16n8k16 — baseline PTX,
// no sm_103a feature suffix needed). Persistent 128 CTAs x 256 thr.
// CTA (mh, n0): C[mh*128..+128, n0..n0+16] per GEMM, hi/lo bf16 split
// (3 passes, fp32 accum) for fp32-grade precision. W resident in SMEM,
// state streamed in K=64 tiles via double-buffered cp.async.

#define SEQ    1024
#define BATCH  256
#define INSZ   64
#define SSZ    1024
#define OUTSZ  64
#define NCTA   128
#define NTHR   256
#define NSL    16
#define NTILES 16

// SMEM layout (bytes)
#define AST    144u       // A tile row stride (128B data + 16B pad)
#define ATILE  18432u     // one half (hi or lo): 128 rows * 144
#define ADBUF  36864u
#define WST    2064u      // W row stride (2048B + 16B pad)
#define WHALF  33024u     // 16 rows * 2064 (hi block size = lo offset)
#define W1H    0u
#define W1L    33024u
#define W2H    66048u
#define W2L    99072u
#define A_OFF  132096u
#define BIAS1  205824u
#define BIAS2  205888u
#define SMEM_BYTES 205952u

__device__ __nv_bfloat16 g_Shi[2][BATCH][SSZ];
__device__ __nv_bfloat16 g_Slo[2][BATCH][SSZ];
__device__ float         g_Sf [2][BATCH][SSZ];
__device__ __nv_bfloat16 g_Hh[BATCH][SSZ];
__device__ __nv_bfloat16 g_Hl[BATCH][SSZ];
__device__ unsigned g_grp[16];
__device__ unsigned g_root;
__device__ volatile unsigned g_epoch;

// ---------------- PTX helpers ----------------
__device__ __forceinline__ uint32_t smem_u32(const void* p) {
    uint32_t a;
    asm("{ .reg .u64 t; cvta.to.shared.u64 t, %1; cvt.u32.u64 %0, t; }"
        : "=r"(a) : "l"(p));
    return a;
}
#define CP_ASYNC16(sa, ga) \
    asm volatile("cp.async.cg.shared.global [%0], [%1], 16;" :: "r"(sa), "l"(ga))
#define CP_COMMIT() asm volatile("cp.async.commit_group;" ::: "memory")
#define CP_WAIT0()  asm volatile("cp.async.wait_group 0;" ::: "memory")
#define CP_WAIT1()  asm volatile("cp.async.wait_group 1;" ::: "memory")

__device__ __forceinline__ void ldsm4(uint32_t a[4], uint32_t addr) {
    asm volatile("ldmatrix.sync.aligned.m8n8.x4.shared.b16 {%0,%1,%2,%3}, [%4];"
        : "=r"(a[0]), "=r"(a[1]), "=r"(a[2]), "=r"(a[3]) : "r"(addr));
}
__device__ __forceinline__ void mma16816(float c[4], const uint32_t a[4],
                                         uint32_t b0, uint32_t b1) {
    asm volatile(
        "mma.sync.aligned.m16n8k16.row.col.f32.bf16.bf16.f32 "
        "{%0,%1,%2,%3}, {%4,%5,%6,%7}, {%8,%9}, {%0,%1,%2,%3};"
        : "+f"(c[0]), "+f"(c[1]), "+f"(c[2]), "+f"(c[3])
        : "r"(a[0]), "r"(a[1]), "r"(a[2]), "r"(a[3]), "r"(b0), "r"(b1));
}

// 2-level tree barrier (16 groups x 8), monotonic counters (graph-replay safe)
__device__ __forceinline__ void gbar(unsigned ep0, unsigned idx, int cta) {
    __syncthreads();
    if (threadIdx.x == 0) {
        __threadfence();
        unsigned o = atomicAdd(&g_grp[cta & 15], 1u);
        if ((o & 7u) == 7u) {
            unsigned r = atomicAdd(&g_root, 1u);
            if ((r & 15u) == 15u) {
                __threadfence();
                atomicAdd((unsigned*)&g_epoch, 1u);
            }
        }
        while ((unsigned)(g_epoch - ep0) < idx) { }
        __threadfence();
    }
    __syncthreads();
}

__device__ __forceinline__ void split_bf(float v, __nv_bfloat16& h, __nv_bfloat16& l) {
    h = __float2bfloat16(v);
    l = __float2bfloat16(v - __bfloat162float(h));
}
__device__ __forceinline__ uint32_t pk(__nv_bfloat16 a, __nv_bfloat16 b) {
    return (uint32_t)__bfloat16_as_ushort(a) | ((uint32_t)__bfloat16_as_ushort(b) << 16);
}

// stage one K=64 tile (hi+lo) of A into SMEM buffer bsel
__device__ __forceinline__ void stageA(uint32_t su, int bsel,
                                       const __nv_bfloat16* __restrict__ gh,
                                       const __nv_bfloat16* __restrict__ gl,
                                       int t, int tid) {
    const uint32_t abase = su + A_OFF + (uint32_t)bsel * ADBUF;
#pragma unroll
    for (int j = 0; j < 8; ++j) {
        int c    = tid + j * NTHR;      // 0..2047
        int half = c >> 10;             // 0=hi 1=lo
        int cc   = c & 1023;
        int row  = cc >> 3;
        int k8   = cc & 7;
        const __nv_bfloat16* gp = (half ? gl : gh) + row * SSZ + t * 64 + k8 * 8;
        CP_ASYNC16(abase + (uint32_t)half * ATILE + (uint32_t)row * AST
                         + (uint32_t)k8 * 16, gp);
    }
}

// full K=1024 split-GEMM into acc0/acc1 (warp tile M16 x N16)
__device__ __forceinline__ void mma_phase(uint32_t su,
                                          const __nv_bfloat16* __restrict__ gh,
                                          const __nv_bfloat16* __restrict__ gl,
                                          uint32_t wbase, uint32_t at_off,
                                          uint32_t wt_off, int tid,
                                          float acc0[4], float acc1[4]) {
#pragma unroll
    for (int i = 0; i < 4; ++i) { acc0[i] = 0.0f; acc1[i] = 0.0f; }

    stageA(su, 0, gh, gl, 0, tid);
    CP_COMMIT();
#pragma unroll 1
    for (int tt = 0; tt < NTILES; ++tt) {
        if (tt < NTILES - 1) {
            stageA(su, (tt + 1) & 1, gh, gl, tt + 1, tid);
            CP_COMMIT();
            CP_WAIT1();
        } else {
            CP_WAIT0();
        }
        __syncthreads();

        const uint32_t ab = su + A_OFF + (uint32_t)(tt & 1) * ADBUF + at_off;
        const uint32_t wb = wbase + wt_off + (uint32_t)tt * 128;
#pragma unroll
        for (int j = 0; j < 4; ++j) {
            uint32_t Ah[4], Al[4], Wh[4], Wl[4];
            ldsm4(Ah, ab + j * 32);
            ldsm4(Al, ab + j * 32 + ATILE);
            ldsm4(Wh, wb + j * 32);
            ldsm4(Wl, wb + j * 32 + WHALF);
            mma16816(acc0, Ah, Wh[0], Wh[1]);
            mma16816(acc1, Ah, Wh[2], Wh[3]);
            mma16816(acc0, Ah, Wl[0], Wl[1]);
            mma16816(acc1, Ah, Wl[2], Wl[3]);
            mma16816(acc0, Al, Wh[0], Wh[1]);
            mma16816(acc1, Al, Wh[2], Wh[3]);
        }
        __syncthreads();
    }
}

__global__ __launch_bounds__(NTHR, 1)
void resrnn_kernel(const float* __restrict__ x,
                   const float* __restrict__ W1,
                   const float* __restrict__ b1,
                   const float* __restrict__ W2,
                   const float* __restrict__ b2,
                   float* __restrict__ out)
{
    extern __shared__ char smem[];
    const uint32_t su = smem_u32(smem);

    const int tid  = threadIdx.x;
    const int wid  = tid >> 5;
    const int lane = tid & 31;
    const int cta  = blockIdx.x;
    const int mh   = cta & 1;
    const int n0   = (cta >> 1) * NSL;

    const unsigned ep0 = g_epoch;

    // ---- stage W slices (fp32 -> bf16 hi/lo, padded row-major) ----
    for (int m = 0; m < 2; ++m) {
        const float* W = m ? W2 : W1;
        uint32_t hoff = m ? W2H : W1H;
        for (int idx = tid; idx < NSL * SSZ; idx += NTHR) {
            int n = idx >> 10, k = idx & (SSZ - 1);
            float w = W[(size_t)(n0 + n) * SSZ + k];
            __nv_bfloat16 wh, wl; split_bf(w, wh, wl);
            uint32_t o = (uint32_t)n * WST + (uint32_t)k * 2;
            *(__nv_bfloat16*)(smem + hoff + o)         = wh;
            *(__nv_bfloat16*)(smem + hoff + WHALF + o) = wl;
        }
    }
    {
        float* b1s = (float*)(smem + BIAS1);
        float* b2s = (float*)(smem + BIAS2);
        if (tid < NSL) { b1s[tid] = b1[n0 + tid]; b2s[tid] = b2[n0 + tid]; }
    }
    // ---- init S0 (own slice): [x0, zeros], fp32 master + mirrors ----
    for (int idx = tid; idx < 128 * NSL; idx += NTHR) {
        int bb = idx >> 4, c = idx & (NSL - 1);
        int b = mh * 128 + bb, k = n0 + c;
        float v = (k < INSZ) ? x[(size_t)b * INSZ + k] : 0.0f;
        g_Sf[0][b][k] = v;
        __nv_bfloat16 vh, vl; split_bf(v, vh, vl);
        g_Shi[0][b][k] = vh;
        g_Slo[0][b][k] = vl;
    }
    unsigned bc = 0;
    gbar(ep0, ++bc, cta);

    // ldmatrix per-thread address offsets
    const uint32_t at_off =
        (uint32_t)(16 * wid + ((lane >> 3) & 1) * 8 + (lane & 7)) * AST
        + (uint32_t)((lane >> 4) & 1) * 16;
    const uint32_t wt_off =
        (uint32_t)((lane & 7) + ((lane >> 4) & 1) * 8) * WST
        + (uint32_t)((lane >> 3) & 1) * 16;

    const int gr = lane >> 2;
    const int gc = 2 * (lane & 3);
    const float* b1s = (const float*)(smem + BIAS1);
    const float* b2s = (const float*)(smem + BIAS2);
    const float p = 0.97f;
    const float q = 1.0f - 0.97f;

    for (int t = 0; t < SEQ; ++t) {
        const int cur = t & 1, nxt = (t + 1) & 1;

        // ============ Phase 1: H = |S @ W1^T + b1| ============
        {
            float acc0[4], acc1[4];
            mma_phase(su, &g_Shi[cur][mh * 128][0], &g_Slo[cur][mh * 128][0],
                      su + W1H, at_off, wt_off, tid, acc0, acc1);
#pragma unroll
            for (int nt = 0; nt < 2; ++nt) {
                const float* acc = nt ? acc1 : acc0;
                int c = 8 * nt + gc;
#pragma unroll
                for (int h = 0; h < 2; ++h) {
                    int b = mh * 128 + 16 * wid + gr + h * 8;
                    float v0 = fabsf(acc[2 * h]     + b1s[c]);
                    float v1 = fabsf(acc[2 * h + 1] + b1s[c + 1]);
                    __nv_bfloat16 h0, l0, h1, l1;
                    split_bf(v0, h0, l0); split_bf(v1, h1, l1);
                    *(uint32_t*)&g_Hh[b][n0 + c] = pk(h0, h1);
                    *(uint32_t*)&g_Hl[b][n0 + c] = pk(l0, l1);
                }
            }
        }
        gbar(ep0, ++bc, cta);

        // ============ Phase 2: S' = p*S + q*(H @ W2^T + b2) ============
        {
            float acc0[4], acc1[4];
            mma_phase(su, &g_Hh[mh * 128][0], &g_Hl[mh * 128][0],
                      su + W2H, at_off, wt_off, tid, acc0, acc1);
#pragma unroll
            for (int nt = 0; nt < 2; ++nt) {
                const float* acc = nt ? acc1 : acc0;
                int c = 8 * nt + gc;
#pragma unroll
                for (int h = 0; h < 2; ++h) {
                    int b = mh * 128 + 16 * wid + gr + h * 8;
                    float2 sold = *(const float2*)&g_Sf[cur][b][n0 + c];
                    float n0v = p * sold.x + q * (acc[2 * h]     + b2s[c]);
                    float n1v = p * sold.y + q * (acc[2 * h + 1] + b2s[c + 1]);
                    if (n0 < SSZ - INSZ) {
                        *(float2*)&g_Sf[nxt][b][n0 + INSZ + c] = make_float2(n0v, n1v);
                        __nv_bfloat16 h0, l0, h1, l1;
                        split_bf(n0v, h0, l0); split_bf(n1v, h1, l1);
                        *(uint32_t*)&g_Shi[nxt][b][n0 + INSZ + c] = pk(h0, h1);
                        *(uint32_t*)&g_Slo[nxt][b][n0 + INSZ + c] = pk(l0, l1);
                    }
                    if (t == SEQ - 1 && n0 >= SSZ - OUTSZ) {
                        *(float2*)&out[(size_t)b * OUTSZ + (n0 - (SSZ - OUTSZ)) + c] =
                            make_float2(n0v, n1v);
                    }
                }
            }
            // inject x_{t+1} into cols [n0, n0+16) for n0 < 64
            if (n0 < INSZ && t + 1 < SEQ) {
                const float* xp = x + (size_t)(t + 1) * BATCH * INSZ;
                for (int idx = tid; idx < 128 * NSL; idx += NTHR) {
                    int bb = idx >> 4, c = idx & (NSL - 1);
                    int b = mh * 128 + bb, k = n0 + c;
                    float v = xp[(size_t)b * INSZ + k];
                    g_Sf[nxt][b][k] = v;
                    __nv_bfloat16 vh, vl; split_bf(v, vh, vl);
                    g_Shi[nxt][b][k] = vh;
                    g_Slo[nxt][b][k] = vl;
                }
            }
        }
        gbar(ep0, ++bc, cta);
    }
}

extern "C" void kernel_launch(void* const* d_in, const int* in_sizes, int n_in,
                              void* d_out, int out_size) {
    (void)in_sizes; (void)n_in; (void)out_size;
    const float* x  = (const float*)d_in[0];
    const float* W1 = (const float*)d_in[1];
    const float* b1 = (const float*)d_in[2];
    const float* W2 = (const float*)d_in[3];
    const float* b2 = (const float*)d_in[4];

    cudaFuncSetAttribute(resrnn_kernel,
                         cudaFuncAttributeMaxDynamicSharedMemorySize,
                         (int)SMEM_BYTES);
    resrnn_kernel<<<NCTA, NTHR, SMEM_BYTES>>>(x, W1, b1, W2, b2, (float*)d_out);
}

// round 10
// speedup vs baseline: 1.8176x; 1.0489x over previous
#include <cuda_runtime.h>
#include <cuda_bf16.h>
#include <cstdint>

// ResRnn via warp-level bf16 mma.sync. R10: 128 CTAs x 1024 thr (occ 50%).
// 32 warps = 8 M-warps x 4 j-groups; all groups consume the same staged
// K=64 A tile (j-chunk split => no extra SMEM); 4-way K-partial reduction
// through SMEM aliased over A staging buffer 0.

#define SEQ    1024
#define BATCH  256
#define INSZ   64
#define SSZ    1024
#define OUTSZ  64
#define NCTA   128
#define NTHR   1024
#define NSL    16
#define NTILES 16

// SMEM layout (bytes)
#define AST    144u       // A tile row stride (128B data + 16B pad)
#define ATILE  18432u     // one half (hi or lo): 128 rows * 144
#define ADBUF  36864u
#define WST    2064u      // W row stride (2048B + 16B pad)
#define WHALF  33024u
#define W1H    0u
#define W1L    33024u
#define W2H    66048u
#define W2L    99072u
#define A_OFF  132096u
#define BIAS1  205824u
#define BIAS2  205888u
#define SMEM_BYTES 205952u

__device__ __nv_bfloat16 g_Shi[2][BATCH][SSZ];
__device__ __nv_bfloat16 g_Slo[2][BATCH][SSZ];
__device__ float         g_Sf [2][BATCH][SSZ];
__device__ __nv_bfloat16 g_Hh[BATCH][SSZ];
__device__ __nv_bfloat16 g_Hl[BATCH][SSZ];
__device__ unsigned g_grp[16];
__device__ unsigned g_root;
__device__ volatile unsigned g_epoch;

// ---------------- PTX helpers ----------------
__device__ __forceinline__ uint32_t smem_u32(const void* p) {
    uint32_t a;
    asm("{ .reg .u64 t; cvta.to.shared.u64 t, %1; cvt.u32.u64 %0, t; }"
        : "=r"(a) : "l"(p));
    return a;
}
#define CP_ASYNC16(sa, ga) \
    asm volatile("cp.async.cg.shared.global [%0], [%1], 16;" :: "r"(sa), "l"(ga))
#define CP_COMMIT() asm volatile("cp.async.commit_group;" ::: "memory")
#define CP_WAIT0()  asm volatile("cp.async.wait_group 0;" ::: "memory")
#define CP_WAIT1()  asm volatile("cp.async.wait_group 1;" ::: "memory")

__device__ __forceinline__ void ldsm4(uint32_t a[4], uint32_t addr) {
    asm volatile("ldmatrix.sync.aligned.m8n8.x4.shared.b16 {%0,%1,%2,%3}, [%4];"
        : "=r"(a[0]), "=r"(a[1]), "=r"(a[2]), "=r"(a[3]) : "r"(addr));
}
__device__ __forceinline__ void mma16816(float c[4], const uint32_t a[4],
                                         uint32_t b0, uint32_t b1) {
    asm volatile(
        "mma.sync.aligned.m16n8k16.row.col.f32.bf16.bf16.f32 "
        "{%0,%1,%2,%3}, {%4,%5,%6,%7}, {%8,%9}, {%0,%1,%2,%3};"
        : "+f"(c[0]), "+f"(c[1]), "+f"(c[2]), "+f"(c[3])
        : "r"(a[0]), "r"(a[1]), "r"(a[2]), "r"(a[3]), "r"(b0), "r"(b1));
}

// 2-level tree barrier (16 groups x 8), monotonic counters (graph-replay safe)
__device__ __forceinline__ void gbar(unsigned ep0, unsigned idx, int cta) {
    __syncthreads();
    if (threadIdx.x == 0) {
        __threadfence();
        unsigned o = atomicAdd(&g_grp[cta & 15], 1u);
        if ((o & 7u) == 7u) {
            unsigned r = atomicAdd(&g_root, 1u);
            if ((r & 15u) == 15u) {
                __threadfence();
                atomicAdd((unsigned*)&g_epoch, 1u);
            }
        }
        while ((unsigned)(g_epoch - ep0) < idx) { }
        __threadfence();
    }
    __syncthreads();
}

__device__ __forceinline__ void split_bf(float v, __nv_bfloat16& h, __nv_bfloat16& l) {
    h = __float2bfloat16(v);
    l = __float2bfloat16(v - __bfloat162float(h));
}
__device__ __forceinline__ uint32_t pk(__nv_bfloat16 a, __nv_bfloat16 b) {
    return (uint32_t)__bfloat16_as_ushort(a) | ((uint32_t)__bfloat16_as_ushort(b) << 16);
}

// stage one K=64 tile (hi+lo): each of 1024 threads does 1 hi + 1 lo chunk
__device__ __forceinline__ void stageA(uint32_t su, int bsel,
                                       const __nv_bfloat16* __restrict__ gh,
                                       const __nv_bfloat16* __restrict__ gl,
                                       int t, int tid) {
    const uint32_t abase = su + A_OFF + (uint32_t)bsel * ADBUF;
    const int row = tid >> 3;
    const int k8  = tid & 7;
    const uint32_t so = abase + (uint32_t)row * AST + (uint32_t)k8 * 16;
    const size_t  go = (size_t)row * SSZ + t * 64 + k8 * 8;
    CP_ASYNC16(so,         gh + go);
    CP_ASYNC16(so + ATILE, gl + go);
}

// K=1024 split-GEMM, this warp handles j-chunk jg of each tile.
__device__ __forceinline__ void mma_phase(uint32_t su,
                                          const __nv_bfloat16* __restrict__ gh,
                                          const __nv_bfloat16* __restrict__ gl,
                                          uint32_t wbase, uint32_t at_off,
                                          uint32_t wt_off, int tid,
                                          float acc0[4], float acc1[4]) {
#pragma unroll
    for (int i = 0; i < 4; ++i) { acc0[i] = 0.0f; acc1[i] = 0.0f; }

    stageA(su, 0, gh, gl, 0, tid);
    CP_COMMIT();
#pragma unroll 1
    for (int tt = 0; tt < NTILES; ++tt) {
        if (tt < NTILES - 1) {
            stageA(su, (tt + 1) & 1, gh, gl, tt + 1, tid);
            CP_COMMIT();
            CP_WAIT1();
        } else {
            CP_WAIT0();
        }
        __syncthreads();

        const uint32_t ab = su + A_OFF + (uint32_t)(tt & 1) * ADBUF + at_off;
        const uint32_t wb = wbase + wt_off + (uint32_t)tt * 128;
        uint32_t Ah[4], Al[4], Wh[4], Wl[4];
        ldsm4(Ah, ab);
        ldsm4(Al, ab + ATILE);
        ldsm4(Wh, wb);
        ldsm4(Wl, wb + WHALF);
        mma16816(acc0, Ah, Wh[0], Wh[1]);
        mma16816(acc1, Ah, Wh[2], Wh[3]);
        mma16816(acc0, Ah, Wl[0], Wl[1]);
        mma16816(acc1, Ah, Wl[2], Wl[3]);
        mma16816(acc0, Al, Wh[0], Wh[1]);
        mma16816(acc1, Al, Wh[2], Wh[3]);
        __syncthreads();
    }
}

// 4-way K-partial reduction through SMEM (aliased over A buffer 0).
__device__ __forceinline__ void kreduce(uint32_t su, int jg, int m, int lane,
                                        float acc0[4], float acc1[4]) {
    const uint32_t red = su + A_OFF;
    const uint32_t slot = (uint32_t)(m * 32 + lane) * 32u;   // 8 floats = 32B
    if (jg > 0) {
        float4* p = (float4*)(uintptr_t)0;  // placeholder avoided; use asm-free store
        uint32_t o = red + (uint32_t)(jg - 1) * 8192u + slot;
        asm volatile("st.shared.v4.f32 [%0], {%1,%2,%3,%4};" ::
            "r"(o), "f"(acc0[0]), "f"(acc0[1]), "f"(acc0[2]), "f"(acc0[3]));
        asm volatile("st.shared.v4.f32 [%0], {%1,%2,%3,%4};" ::
            "r"(o + 16u), "f"(acc1[0]), "f"(acc1[1]), "f"(acc1[2]), "f"(acc1[3]));
        (void)p;
    }
    __syncthreads();
    if (jg == 0) {
#pragma unroll
        for (int g = 1; g < 4; ++g) {
            uint32_t o = red + (uint32_t)(g - 1) * 8192u + slot;
            float r0, r1, r2, r3, r4, r5, r6, r7;
            asm volatile("ld.shared.v4.f32 {%0,%1,%2,%3}, [%4];"
                : "=f"(r0), "=f"(r1), "=f"(r2), "=f"(r3) : "r"(o));
            asm volatile("ld.shared.v4.f32 {%0,%1,%2,%3}, [%4];"
                : "=f"(r4), "=f"(r5), "=f"(r6), "=f"(r7) : "r"(o + 16u));
            acc0[0] += r0; acc0[1] += r1; acc0[2] += r2; acc0[3] += r3;
            acc1[0] += r4; acc1[1] += r5; acc1[2] += r6; acc1[3] += r7;
        }
    }
}

__global__ __launch_bounds__(NTHR, 1)
void resrnn_kernel(const float* __restrict__ x,
                   const float* __restrict__ W1,
                   const float* __restrict__ b1,
                   const float* __restrict__ W2,
                   const float* __restrict__ b2,
                   float* __restrict__ out)
{
    extern __shared__ char smem[];
    const uint32_t su = smem_u32(smem);

    const int tid  = threadIdx.x;
    const int wid  = tid >> 5;
    const int lane = tid & 31;
    const int m    = wid & 7;            // M-warp: rows 16*m .. +16
    const int jg   = wid >> 3;           // j-group: K chunk 16*jg within tile
    const int cta  = blockIdx.x;
    const int mh   = cta & 1;
    const int n0   = (cta >> 1) * NSL;

    const unsigned ep0 = g_epoch;

    // ---- stage W slices (fp32 -> bf16 hi/lo, padded row-major) ----
    for (int mi = 0; mi < 2; ++mi) {
        const float* W = mi ? W2 : W1;
        uint32_t hoff = mi ? W2H : W1H;
        for (int idx = tid; idx < NSL * SSZ; idx += NTHR) {
            int n = idx >> 10, k = idx & (SSZ - 1);
            float w = W[(size_t)(n0 + n) * SSZ + k];
            __nv_bfloat16 wh, wl; split_bf(w, wh, wl);
            uint32_t o = (uint32_t)n * WST + (uint32_t)k * 2;
            *(__nv_bfloat16*)(smem + hoff + o)         = wh;
            *(__nv_bfloat16*)(smem + hoff + WHALF + o) = wl;
        }
    }
    {
        float* b1s = (float*)(smem + BIAS1);
        float* b2s = (float*)(smem + BIAS2);
        if (tid < NSL) { b1s[tid] = b1[n0 + tid]; b2s[tid] = b2[n0 + tid]; }
    }
    // ---- init S0 (own slice): [x0, zeros], fp32 master + mirrors ----
    for (int idx = tid; idx < 128 * NSL; idx += NTHR) {
        int bb = idx >> 4, c = idx & (NSL - 1);
        int b = mh * 128 + bb, k = n0 + c;
        float v = (k < INSZ) ? x[(size_t)b * INSZ + k] : 0.0f;
        g_Sf[0][b][k] = v;
        __nv_bfloat16 vh, vl; split_bf(v, vh, vl);
        g_Shi[0][b][k] = vh;
        g_Slo[0][b][k] = vl;
    }
    unsigned bc = 0;
    gbar(ep0, ++bc, cta);

    // ldmatrix per-thread address offsets (jg folded in)
    const uint32_t at_off =
        (uint32_t)(16 * m + ((lane >> 3) & 1) * 8 + (lane & 7)) * AST
        + (uint32_t)((lane >> 4) & 1) * 16
        + (uint32_t)jg * 32;
    const uint32_t wt_off =
        (uint32_t)((lane & 7) + ((lane >> 4) & 1) * 8) * WST
        + (uint32_t)((lane >> 3) & 1) * 16
        + (uint32_t)jg * 32;

    const int gr = lane >> 2;
    const int gc = 2 * (lane & 3);
    const float* b1s = (const float*)(smem + BIAS1);
    const float* b2s = (const float*)(smem + BIAS2);
    const float p = 0.97f;
    const float q = 1.0f - 0.97f;

    for (int t = 0; t < SEQ; ++t) {
        const int cur = t & 1, nxt = (t + 1) & 1;

        // ============ Phase 1: H = |S @ W1^T + b1| ============
        {
            float acc0[4], acc1[4];
            mma_phase(su, &g_Shi[cur][mh * 128][0], &g_Slo[cur][mh * 128][0],
                      su + W1H, at_off, wt_off, tid, acc0, acc1);
            kreduce(su, jg, m, lane, acc0, acc1);
            if (jg == 0) {
#pragma unroll
                for (int nt = 0; nt < 2; ++nt) {
                    const float* acc = nt ? acc1 : acc0;
                    int c = 8 * nt + gc;
#pragma unroll
                    for (int h = 0; h < 2; ++h) {
                        int b = mh * 128 + 16 * m + gr + h * 8;
                        float v0 = fabsf(acc[2 * h]     + b1s[c]);
                        float v1 = fabsf(acc[2 * h + 1] + b1s[c + 1]);
                        __nv_bfloat16 h0, l0, h1, l1;
                        split_bf(v0, h0, l0); split_bf(v1, h1, l1);
                        *(uint32_t*)&g_Hh[b][n0 + c] = pk(h0, h1);
                        *(uint32_t*)&g_Hl[b][n0 + c] = pk(l0, l1);
                    }
                }
            }
        }
        gbar(ep0, ++bc, cta);

        // ============ Phase 2: S' = p*S + q*(H @ W2^T + b2) ============
        {
            float acc0[4], acc1[4];
            mma_phase(su, &g_Hh[mh * 128][0], &g_Hl[mh * 128][0],
                      su + W2H, at_off, wt_off, tid, acc0, acc1);
            kreduce(su, jg, m, lane, acc0, acc1);
            if (jg == 0) {
#pragma unroll
                for (int nt = 0; nt < 2; ++nt) {
                    const float* acc = nt ? acc1 : acc0;
                    int c = 8 * nt + gc;
#pragma unroll
                    for (int h = 0; h < 2; ++h) {
                        int b = mh * 128 + 16 * m + gr + h * 8;
                        float2 sold = *(const float2*)&g_Sf[cur][b][n0 + c];
                        float n0v = p * sold.x + q * (acc[2 * h]     + b2s[c]);
                        float n1v = p * sold.y + q * (acc[2 * h + 1] + b2s[c + 1]);
                        if (n0 < SSZ - INSZ) {
                            *(float2*)&g_Sf[nxt][b][n0 + INSZ + c] = make_float2(n0v, n1v);
                            __nv_bfloat16 h0, l0, h1, l1;
                            split_bf(n0v, h0, l0); split_bf(n1v, h1, l1);
                            *(uint32_t*)&g_Shi[nxt][b][n0 + INSZ + c] = pk(h0, h1);
                            *(uint32_t*)&g_Slo[nxt][b][n0 + INSZ + c] = pk(l0, l1);
                        }
                        if (t == SEQ - 1 && n0 >= SSZ - OUTSZ) {
                            *(float2*)&out[(size_t)b * OUTSZ + (n0 - (SSZ - OUTSZ)) + c] =
                                make_float2(n0v, n1v);
                        }
                    }
                }
            }
            // inject x_{t+1} into cols [n0, n0+16) for n0 < 64 (j-group 1)
            if (n0 < INSZ && t + 1 < SEQ && jg == 1) {
                const float* xp = x + (size_t)(t + 1) * BATCH * INSZ;
                for (int idx = (tid & 255); idx < 128 * NSL; idx += 256) {
                    int bb = idx >> 4, c = idx & (NSL - 1);
                    int b = mh * 128 + bb, k = n0 + c;
                    float v = xp[(size_t)b * INSZ + k];
                    g_Sf[nxt][b][k] = v;
                    __nv_bfloat16 vh, vl; split_bf(v, vh, vl);
                    g_Shi[nxt][b][k] = vh;
                    g_Slo[nxt][b][k] = vl;
                }
            }
        }
        gbar(ep0, ++bc, cta);
    }
}

extern "C" void kernel_launch(void* const* d_in, const int* in_sizes, int n_in,
                              void* d_out, int out_size) {
    (void)in_sizes; (void)n_in; (void)out_size;
    const float* x  = (const float*)d_in[0];
    const float* W1 = (const float*)d_in[1];
    const float* b1 = (const float*)d_in[2];
    const float* W2 = (const float*)d_in[3];
    const float* b2 = (const float*)d_in[4];

    cudaFuncSetAttribute(resrnn_kernel,
                         cudaFuncAttributeMaxDynamicSharedMemorySize,
                         (int)SMEM_BYTES);
    resrnn_kernel<<<NCTA, NTHR, SMEM_BYTES>>>(x, W1, b1, W2, b2, (float*)d_out);
}

// round 11
// speedup vs baseline: 2.0281x; 1.1158x over previous
#include <cuda_runtime.h>
#include <cuda_bf16.h>
#include <cstdint>

// ResRnn via warp-level bf16 mma.sync. R11: sync-free mainloop.
// 128 CTAs x 1024 thr; 32 warps = 8 M-warps x 4 K-quarters. Each warp
// stages its own 16-row x 16-K A fragment (hi+lo, XOR-swizzled) into a
// private double buffer -> produce/consume is warp-local (wait_group +
// syncwarp), zero CTA-wide barriers across the 16-step K loop.

#define SEQ    1024
#define BATCH  256
#define INSZ   64
#define SSZ    1024
#define OUTSZ  64
#define NCTA   128
#define NTHR   1024
#define NSL    16
#define NSTEP  16        // K-steps per warp (K16 each; warp covers K=256)

// SMEM layout (bytes)
#define W1B    0u        // W1: hi 32768 + lo 32768 (rows 2048B, XOR swizzle)
#define W2B    65536u
#define WLO    32768u
#define A_OFF  131072u   // 32 warps x 2 bufs x 1024B (hi 512 + lo 512)
#define RED    196608u   // 3 x 8192 K-partial reduction
#define BIAS1  221184u
#define BIAS2  221248u
#define SMEM_BYTES 221312u

__device__ __nv_bfloat16 g_Shi[2][BATCH][SSZ];
__device__ __nv_bfloat16 g_Slo[2][BATCH][SSZ];
__device__ float         g_Sf [2][BATCH][SSZ];
__device__ __nv_bfloat16 g_Hh[BATCH][SSZ];
__device__ __nv_bfloat16 g_Hl[BATCH][SSZ];
__device__ unsigned g_grp[16];
__device__ unsigned g_root;
__device__ volatile unsigned g_epoch;

// ---------------- PTX helpers ----------------
__device__ __forceinline__ uint32_t smem_u32(const void* p) {
    uint32_t a;
    asm("{ .reg .u64 t; cvta.to.shared.u64 t, %1; cvt.u32.u64 %0, t; }"
        : "=r"(a) : "l"(p));
    return a;
}
#define CP_ASYNC16(sa, ga) \
    asm volatile("cp.async.cg.shared.global [%0], [%1], 16;" :: "r"(sa), "l"(ga))
#define CP_COMMIT() asm volatile("cp.async.commit_group;" ::: "memory")
#define CP_WAIT0()  asm volatile("cp.async.wait_group 0;" ::: "memory")
#define CP_WAIT1()  asm volatile("cp.async.wait_group 1;" ::: "memory")

__device__ __forceinline__ void ldsm4(uint32_t a[4], uint32_t addr) {
    asm volatile("ldmatrix.sync.aligned.m8n8.x4.shared.b16 {%0,%1,%2,%3}, [%4];"
        : "=r"(a[0]), "=r"(a[1]), "=r"(a[2]), "=r"(a[3]) : "r"(addr));
}
__device__ __forceinline__ void mma16816(float c[4], const uint32_t a[4],
                                         uint32_t b0, uint32_t b1) {
    asm volatile(
        "mma.sync.aligned.m16n8k16.row.col.f32.bf16.bf16.f32 "
        "{%0,%1,%2,%3}, {%4,%5,%6,%7}, {%8,%9}, {%0,%1,%2,%3};"
        : "+f"(c[0]), "+f"(c[1]), "+f"(c[2]), "+f"(c[3])
        : "r"(a[0]), "r"(a[1]), "r"(a[2]), "r"(a[3]), "r"(b0), "r"(b1));
}

// 2-level tree barrier (16 groups x 8), monotonic (graph-replay safe)
__device__ __forceinline__ void gbar(unsigned ep0, unsigned idx, int cta) {
    __syncthreads();
    if (threadIdx.x == 0) {
        __threadfence();
        unsigned o = atomicAdd(&g_grp[cta & 15], 1u);
        if ((o & 7u) == 7u) {
            unsigned r = atomicAdd(&g_root, 1u);
            if ((r & 15u) == 15u) {
                __threadfence();
                atomicAdd((unsigned*)&g_epoch, 1u);
            }
        }
        while ((unsigned)(g_epoch - ep0) < idx) { }
        __threadfence();
    }
    __syncthreads();
}

__device__ __forceinline__ void split_bf(float v, __nv_bfloat16& h, __nv_bfloat16& l) {
    h = __float2bfloat16(v);
    l = __float2bfloat16(v - __bfloat162float(h));
}
__device__ __forceinline__ uint32_t pk(__nv_bfloat16 a, __nv_bfloat16 b) {
    return (uint32_t)__bfloat16_as_ushort(a) | ((uint32_t)__bfloat16_as_ushort(b) << 16);
}

// K=256 slice GEMM for one warp: 16 steps of K16, warp-local double buffer.
// awarp: this warp's A buffer base; a_stg/a_cons: per-lane swizzled offsets;
// gofs: per-lane gmem element offset (row*SSZ + jg*256 + h*8);
// wthr: su + n*2048 per-lane W row base (phase base added by caller);
// nx = n&7; c16b = jg*32 + h (logical 16B-chunk base incl. lane k-half).
__device__ __forceinline__ void mma_phase(
    const __nv_bfloat16* __restrict__ gh,
    const __nv_bfloat16* __restrict__ gl,
    uint32_t awarp, uint32_t a_stg, uint32_t a_cons,
    size_t gofs, uint32_t wthr, uint32_t nx, uint32_t c16b,
    float acc0[4], float acc1[4])
{
#pragma unroll
    for (int i = 0; i < 4; ++i) { acc0[i] = 0.0f; acc1[i] = 0.0f; }

    CP_ASYNC16(awarp + a_stg,        (const char*)(gh + gofs));
    CP_ASYNC16(awarp + 512 + a_stg,  (const char*)(gl + gofs));
    CP_COMMIT();

#pragma unroll 1
    for (int st = 0; st < NSTEP; ++st) {
        if (st < NSTEP - 1) {
            const uint32_t ab = awarp + (uint32_t)((st + 1) & 1) * 1024u;
            const size_t   go = gofs + (size_t)(st + 1) * 16;
            CP_ASYNC16(ab + a_stg,       (const char*)(gh + go));
            CP_ASYNC16(ab + 512 + a_stg, (const char*)(gl + go));
            CP_COMMIT();
            CP_WAIT1();
        } else {
            CP_WAIT0();
        }
        __syncwarp();

        uint32_t Ah[4], Al[4], Wh[4], Wl[4];
        const uint32_t ac = awarp + (uint32_t)(st & 1) * 1024u + a_cons;
        ldsm4(Ah, ac);
        ldsm4(Al, ac + 512);
        const uint32_t c16 = c16b + 2u * (uint32_t)st;
        const uint32_t wa  = wthr + (((c16 ^ nx)) << 4);
        ldsm4(Wh, wa);
        ldsm4(Wl, wa + WLO);
        mma16816(acc0, Ah, Wh[0], Wh[1]);
        mma16816(acc1, Ah, Wh[2], Wh[3]);
        mma16816(acc0, Ah, Wl[0], Wl[1]);
        mma16816(acc1, Ah, Wl[2], Wl[3]);
        mma16816(acc0, Al, Wh[0], Wh[1]);
        mma16816(acc1, Al, Wh[2], Wh[3]);
    }
}

// 4-way K-partial reduction through dedicated SMEM region.
__device__ __forceinline__ void kreduce(uint32_t su, int jg, int m, int lane,
                                        float acc0[4], float acc1[4]) {
    const uint32_t slot = (uint32_t)(m * 32 + lane) * 32u;
    if (jg > 0) {
        uint32_t o = su + RED + (uint32_t)(jg - 1) * 8192u + slot;
        asm volatile("st.shared.v4.f32 [%0], {%1,%2,%3,%4};" ::
            "r"(o), "f"(acc0[0]), "f"(acc0[1]), "f"(acc0[2]), "f"(acc0[3]));
        asm volatile("st.shared.v4.f32 [%0], {%1,%2,%3,%4};" ::
            "r"(o + 16u), "f"(acc1[0]), "f"(acc1[1]), "f"(acc1[2]), "f"(acc1[3]));
    }
    __syncthreads();
    if (jg == 0) {
#pragma unroll
        for (int g = 1; g < 4; ++g) {
            uint32_t o = su + RED + (uint32_t)(g - 1) * 8192u + slot;
            float r0, r1, r2, r3, r4, r5, r6, r7;
            asm volatile("ld.shared.v4.f32 {%0,%1,%2,%3}, [%4];"
                : "=f"(r0), "=f"(r1), "=f"(r2), "=f"(r3) : "r"(o));
            asm volatile("ld.shared.v4.f32 {%0,%1,%2,%3}, [%4];"
                : "=f"(r4), "=f"(r5), "=f"(r6), "=f"(r7) : "r"(o + 16u));
            acc0[0] += r0; acc0[1] += r1; acc0[2] += r2; acc0[3] += r3;
            acc1[0] += r4; acc1[1] += r5; acc1[2] += r6; acc1[3] += r7;
        }
    }
}

__global__ __launch_bounds__(NTHR, 1)
void resrnn_kernel(const float* __restrict__ x,
                   const float* __restrict__ W1,
                   const float* __restrict__ b1,
                   const float* __restrict__ W2,
                   const float* __restrict__ b2,
                   float* __restrict__ out)
{
    extern __shared__ char smem[];
    const uint32_t su = smem_u32(smem);

    const int tid  = threadIdx.x;
    const int wid  = tid >> 5;
    const int lane = tid & 31;
    const int m    = wid & 7;            // M-warp: batch rows 16m..+16
    const int jg   = wid >> 3;           // K-quarter: K in [jg*256, +256)
    const int cta  = blockIdx.x;
    const int mh   = cta & 1;
    const int n0   = (cta >> 1) * NSL;

    const unsigned ep0 = g_epoch;

    // ---- stage W slices: fp32 -> bf16 hi/lo, 2048B rows + XOR-16B swizzle ----
    for (int mi = 0; mi < 2; ++mi) {
        const float* W = mi ? W2 : W1;
        const uint32_t base = mi ? W2B : W1B;
        for (int idx = tid; idx < NSL * SSZ; idx += NTHR) {
            int n = idx >> 10, k = idx & (SSZ - 1);
            float w = W[(size_t)(n0 + n) * SSZ + k];
            __nv_bfloat16 wh, wl; split_bf(w, wh, wl);
            uint32_t o = (uint32_t)n * 2048u
                       + (uint32_t)(((k >> 3) ^ (n & 7)) << 4)
                       + (uint32_t)((k & 7) << 1);
            *(__nv_bfloat16*)(smem + base + o)       = wh;
            *(__nv_bfloat16*)(smem + base + WLO + o) = wl;
        }
    }
    {
        float* b1s = (float*)(smem + BIAS1);
        float* b2s = (float*)(smem + BIAS2);
        if (tid < NSL) { b1s[tid] = b1[n0 + tid]; b2s[tid] = b2[n0 + tid]; }
    }
    // ---- init S0 (own slice): [x0, zeros] ----
    for (int idx = tid; idx < 128 * NSL; idx += NTHR) {
        int bb = idx >> 4, c = idx & (NSL - 1);
        int b = mh * 128 + bb, k = n0 + c;
        float v = (k < INSZ) ? x[(size_t)b * INSZ + k] : 0.0f;
        g_Sf[0][b][k] = v;
        __nv_bfloat16 vh, vl; split_bf(v, vh, vl);
        g_Shi[0][b][k] = vh;
        g_Slo[0][b][k] = vl;
    }
    unsigned bc = 0;
    gbar(ep0, ++bc, cta);

    // ---- per-lane constant offsets ----
    // A staging: lane -> (row = lane>>1, h = lane&1), 32B rows, XOR by row bit2
    const int s_row = lane >> 1, s_h = lane & 1;
    const uint32_t a_stg = (uint32_t)s_row * 32u
                         + (uint32_t)((s_h ^ ((s_row >> 2) & 1)) << 4);
    const size_t gofs = (size_t)(16 * m + s_row) * SSZ + (size_t)jg * 256 + s_h * 8;
    // A consume (ldmatrix x4): row = (lane&7)+((lane>>3)&1)*8, h = (lane>>4)&1
    {
    }
    const int c_row = (lane & 7) + ((lane >> 3) & 1) * 8;
    const int c_h   = (lane >> 4) & 1;
    const uint32_t a_cons = (uint32_t)c_row * 32u
                          + (uint32_t)((c_h ^ ((c_row >> 2) & 1)) << 4);
    const uint32_t awarp = su + A_OFF + (uint32_t)wid * 2048u;
    // W consume: n = (lane&7)+((lane>>4)&1)*8, h = (lane>>3)&1
    const uint32_t wn  = (uint32_t)((lane & 7) + ((lane >> 4) & 1) * 8);
    const uint32_t nx  = wn & 7u;
    const uint32_t wrow = wn * 2048u;
    const uint32_t c16b = (uint32_t)jg * 32u + (uint32_t)((lane >> 3) & 1);

    const int gr = lane >> 2;
    const int gc = 2 * (lane & 3);
    const float* b1s = (const float*)(smem + BIAS1);
    const float* b2s = (const float*)(smem + BIAS2);
    const float p = 0.97f;
    const float q = 1.0f - 0.97f;

    for (int t = 0; t < SEQ; ++t) {
        const int cur = t & 1, nxt = (t + 1) & 1;

        // ============ Phase 1: H = |S @ W1^T + b1| ============
        {
            float acc0[4], acc1[4];
            mma_phase(&g_Shi[cur][mh * 128][0], &g_Slo[cur][mh * 128][0],
                      awarp, a_stg, a_cons, gofs,
                      su + W1B + wrow, nx, c16b, acc0, acc1);
            kreduce(su, jg, m, lane, acc0, acc1);
            if (jg == 0) {
#pragma unroll
                for (int nt = 0; nt < 2; ++nt) {
                    const float* acc = nt ? acc1 : acc0;
                    int c = 8 * nt + gc;
#pragma unroll
                    for (int h = 0; h < 2; ++h) {
                        int b = mh * 128 + 16 * m + gr + h * 8;
                        float v0 = fabsf(acc[2 * h]     + b1s[c]);
                        float v1 = fabsf(acc[2 * h + 1] + b1s[c + 1]);
                        __nv_bfloat16 h0, l0, h1, l1;
                        split_bf(v0, h0, l0); split_bf(v1, h1, l1);
                        *(uint32_t*)&g_Hh[b][n0 + c] = pk(h0, h1);
                        *(uint32_t*)&g_Hl[b][n0 + c] = pk(l0, l1);
                    }
                }
            }
        }
        gbar(ep0, ++bc, cta);

        // ============ Phase 2: S' = p*S + q*(H @ W2^T + b2) ============
        {
            float acc0[4], acc1[4];
            mma_phase(&g_Hh[mh * 128][0], &g_Hl[mh * 128][0],
                      awarp, a_stg, a_cons, gofs,
                      su + W2B + wrow, nx, c16b, acc0, acc1);
            kreduce(su, jg, m, lane, acc0, acc1);
            if (jg == 0) {
#pragma unroll
                for (int nt = 0; nt < 2; ++nt) {
                    const float* acc = nt ? acc1 : acc0;
                    int c = 8 * nt + gc;
#pragma unroll
                    for (int h = 0; h < 2; ++h) {
                        int b = mh * 128 + 16 * m + gr + h * 8;
                        float2 sold = *(const float2*)&g_Sf[cur][b][n0 + c];
                        float n0v = p * sold.x + q * (acc[2 * h]     + b2s[c]);
                        float n1v = p * sold.y + q * (acc[2 * h + 1] + b2s[c + 1]);
                        if (n0 < SSZ - INSZ) {
                            *(float2*)&g_Sf[nxt][b][n0 + INSZ + c] = make_float2(n0v, n1v);
                            __nv_bfloat16 h0, l0, h1, l1;
                            split_bf(n0v, h0, l0); split_bf(n1v, h1, l1);
                            *(uint32_t*)&g_Shi[nxt][b][n0 + INSZ + c] = pk(h0, h1);
                            *(uint32_t*)&g_Slo[nxt][b][n0 + INSZ + c] = pk(l0, l1);
                        }
                        if (t == SEQ - 1 && n0 >= SSZ - OUTSZ) {
                            *(float2*)&out[(size_t)b * OUTSZ + (n0 - (SSZ - OUTSZ)) + c] =
                                make_float2(n0v, n1v);
                        }
                    }
                }
            }
            // inject x_{t+1} into cols [n0, n0+16) for n0 < 64 (j-group 1)
            if (n0 < INSZ && t + 1 < SEQ && jg == 1) {
                const float* xp = x + (size_t)(t + 1) * BATCH * INSZ;
                for (int idx = (tid & 255); idx < 128 * NSL; idx += 256) {
                    int bb = idx >> 4, c = idx & (NSL - 1);
                    int b = mh * 128 + bb, k = n0 + c;
                    float v = xp[(size_t)b * INSZ + k];
                    g_Sf[nxt][b][k] = v;
                    __nv_bfloat16 vh, vl; split_bf(v, vh, vl);
                    g_Shi[nxt][b][k] = vh;
                    g_Slo[nxt][b][k] = vl;
                }
            }
        }
        gbar(ep0, ++bc, cta);
    }
}

extern "C" void kernel_launch(void* const* d_in, const int* in_sizes, int n_in,
                              void* d_out, int out_size) {
    (void)in_sizes; (void)n_in; (void)out_size;
    const float* x  = (const float*)d_in[0];
    const float* W1 = (const float*)d_in[1];
    const float* b1 = (const float*)d_in[2];
    const float* W2 = (const float*)d_in[3];
    const float* b2 = (const float*)d_in[4];

    cudaFuncSetAttribute(resrnn_kernel,
                         cudaFuncAttributeMaxDynamicSharedMemorySize,
                         (int)SMEM_BYTES);
    resrnn_kernel<<<NCTA, NTHR, SMEM_BYTES>>>(x, W1, b1, W2, b2, (float*)d_out);
}

// round 12
// speedup vs baseline: 3.2563x; 1.6056x over previous
#include <cuda_runtime.h>
#include <cuda_bf16.h>
#include <cstdint>

// ResRnn via warp-level bf16 mma.sync. R12: fragment-permuted global state.
// S and H are stored in mma-fragment order (per 16x16 tile, lane l owns 16
// contiguous bytes = its 4 A-registers), so each warp K-step is ONE LDG.128
// (hi) + ONE LDG.128 (lo) straight to registers: no cp.async, no A-ldmatrix,
// no staging SMEM, no waits. W stays SMEM-resident (XOR-swizzled ldmatrix).
// 128 CTAs x 1024 thr; 32 warps = 8 M-warps x 4 K-quarters; hi/lo bf16
// split (3 passes, fp32 accum); fp32 master state for the residual.

#define SEQ    1024
#define BATCH  256
#define INSZ   64
#define SSZ    1024
#define OUTSZ  64
#define NCTA   128
#define NTHR   1024
#define NSL    16
#define NSTEP  16

// SMEM layout (bytes)
#define W1B    0u
#define W2B    65536u
#define WLO    32768u
#define RED    131072u    // 3 x 8192 K-partial reduction
#define BIAS1  155648u
#define BIAS2  155712u
#define SMEM_BYTES 155776u

// Fragment-permuted state: [buf][half][mtile 16][ktile 64][lane*4+reg]
__device__ uint32_t g_SP[2][2][16][64][128];
__device__ uint32_t g_HP[2][16][64][128];
__device__ float    g_Sf[2][BATCH][SSZ];
__device__ unsigned g_grp[16];
__device__ unsigned g_root;
__device__ volatile unsigned g_epoch;

// ---------------- PTX helpers ----------------
__device__ __forceinline__ uint32_t smem_u32(const void* p) {
    uint32_t a;
    asm("{ .reg .u64 t; cvta.to.shared.u64 t, %1; cvt.u32.u64 %0, t; }"
        : "=r"(a) : "l"(p));
    return a;
}
__device__ __forceinline__ void ldsm4(uint32_t a[4], uint32_t addr) {
    asm volatile("ldmatrix.sync.aligned.m8n8.x4.shared.b16 {%0,%1,%2,%3}, [%4];"
        : "=r"(a[0]), "=r"(a[1]), "=r"(a[2]), "=r"(a[3]) : "r"(addr));
}
__device__ __forceinline__ void mma16816(float c[4], const uint32_t a0,
                                         const uint32_t a1, const uint32_t a2,
                                         const uint32_t a3,
                                         uint32_t b0, uint32_t b1) {
    asm volatile(
        "mma.sync.aligned.m16n8k16.row.col.f32.bf16.bf16.f32 "
        "{%0,%1,%2,%3}, {%4,%5,%6,%7}, {%8,%9}, {%0,%1,%2,%3};"
        : "+f"(c[0]), "+f"(c[1]), "+f"(c[2]), "+f"(c[3])
        : "r"(a0), "r"(a1), "r"(a2), "r"(a3), "r"(b0), "r"(b1));
}

// 2-level tree barrier (16 groups x 8), monotonic (graph-replay safe)
__device__ __forceinline__ void gbar(unsigned ep0, unsigned idx, int cta) {
    __syncthreads();
    if (threadIdx.x == 0) {
        __threadfence();
        unsigned o = atomicAdd(&g_grp[cta & 15], 1u);
        if ((o & 7u) == 7u) {
            unsigned r = atomicAdd(&g_root, 1u);
            if ((r & 15u) == 15u) {
                __threadfence();
                atomicAdd((unsigned*)&g_epoch, 1u);
            }
        }
        while ((unsigned)(g_epoch - ep0) < idx) { }
        __threadfence();
    }
    __syncthreads();
}

__device__ __forceinline__ void split_bf(float v, __nv_bfloat16& h, __nv_bfloat16& l) {
    h = __float2bfloat16(v);
    l = __float2bfloat16(v - __bfloat162float(h));
}
__device__ __forceinline__ uint32_t pk(__nv_bfloat16 a, __nv_bfloat16 b) {
    return (uint32_t)__bfloat16_as_ushort(a) | ((uint32_t)__bfloat16_as_ushort(b) << 16);
}

// One warp's K=256 slice: 16 steps; A hi/lo via LDG.128 from permuted layout,
// register double-buffered (distance 2); W via swizzled ldmatrix from SMEM.
__device__ __forceinline__ void mma_phase(const uint4* __restrict__ ph,
                                          const uint4* __restrict__ pl,
                                          uint32_t wlane, uint32_t nx, uint32_t c16b,
                                          float acc0[4], float acc1[4])
{
#pragma unroll
    for (int i = 0; i < 4; ++i) { acc0[i] = 0.0f; acc1[i] = 0.0f; }

    uint4 Ah[2], Al[2];
    Ah[0] = ph[0];  Al[0] = pl[0];
    Ah[1] = ph[32]; Al[1] = pl[32];     // ktile stride = 128 words = 32 uint4

#pragma unroll
    for (int st = 0; st < NSTEP; ++st) {
        const int s = st & 1;
        uint32_t Wh[4], Wl[4];
        const uint32_t wa = wlane + (((c16b + 2u * (uint32_t)st) ^ nx) << 4);
        ldsm4(Wh, wa);
        ldsm4(Wl, wa + WLO);
        const uint4 ah = Ah[s];
        const uint4 al = Al[s];
        if (st + 2 < NSTEP) Ah[s] = ph[(st + 2) * 32];
        mma16816(acc0, ah.x, ah.y, ah.z, ah.w, Wh[0], Wh[1]);
        mma16816(acc1, ah.x, ah.y, ah.z, ah.w, Wh[2], Wh[3]);
        mma16816(acc0, ah.x, ah.y, ah.z, ah.w, Wl[0], Wl[1]);
        mma16816(acc1, ah.x, ah.y, ah.z, ah.w, Wl[2], Wl[3]);
        if (st + 2 < NSTEP) Al[s] = pl[(st + 2) * 32];
        mma16816(acc0, al.x, al.y, al.z, al.w, Wh[0], Wh[1]);
        mma16816(acc1, al.x, al.y, al.z, al.w, Wh[2], Wh[3]);
    }
}

// 4-way K-partial reduction through SMEM.
__device__ __forceinline__ void kreduce(uint32_t su, int jg, int m, int lane,
                                        float acc0[4], float acc1[4]) {
    const uint32_t slot = (uint32_t)(m * 32 + lane) * 32u;
    if (jg > 0) {
        uint32_t o = su + RED + (uint32_t)(jg - 1) * 8192u + slot;
        asm volatile("st.shared.v4.f32 [%0], {%1,%2,%3,%4};" ::
            "r"(o), "f"(acc0[0]), "f"(acc0[1]), "f"(acc0[2]), "f"(acc0[3]));
        asm volatile("st.shared.v4.f32 [%0], {%1,%2,%3,%4};" ::
            "r"(o + 16u), "f"(acc1[0]), "f"(acc1[1]), "f"(acc1[2]), "f"(acc1[3]));
    }
    __syncthreads();
    if (jg == 0) {
#pragma unroll
        for (int g = 1; g < 4; ++g) {
            uint32_t o = su + RED + (uint32_t)(g - 1) * 8192u + slot;
            float r0, r1, r2, r3, r4, r5, r6, r7;
            asm volatile("ld.shared.v4.f32 {%0,%1,%2,%3}, [%4];"
                : "=f"(r0), "=f"(r1), "=f"(r2), "=f"(r3) : "r"(o));
            asm volatile("ld.shared.v4.f32 {%0,%1,%2,%3}, [%4];"
                : "=f"(r4), "=f"(r5), "=f"(r6), "=f"(r7) : "r"(o + 16u));
            acc0[0] += r0; acc0[1] += r1; acc0[2] += r2; acc0[3] += r3;
            acc1[0] += r4; acc1[1] += r5; acc1[2] += r6; acc1[3] += r7;
        }
    }
}

__global__ __launch_bounds__(NTHR, 1)
void resrnn_kernel(const float* __restrict__ x,
                   const float* __restrict__ W1,
                   const float* __restrict__ b1,
                   const float* __restrict__ W2,
                   const float* __restrict__ b2,
                   float* __restrict__ out)
{
    extern __shared__ char smem[];
    const uint32_t su = smem_u32(smem);

    const int tid  = threadIdx.x;
    const int wid  = tid >> 5;
    const int lane = tid & 31;
    const int m    = wid & 7;            // M-warp: batch rows 16m..+16 (of mh half)
    const int jg   = wid >> 3;           // K-quarter
    const int cta  = blockIdx.x;
    const int mh   = cta & 1;
    const int n0   = (cta >> 1) * NSL;
    const int mtile = mh * 8 + m;

    const unsigned ep0 = g_epoch;

    // ---- stage W slices: fp32 -> bf16 hi/lo, 2048B rows + XOR-16B swizzle ----
    for (int mi = 0; mi < 2; ++mi) {
        const float* W = mi ? W2 : W1;
        const uint32_t base = mi ? W2B : W1B;
        for (int idx = tid; idx < NSL * SSZ; idx += NTHR) {
            int n = idx >> 10, k = idx & (SSZ - 1);
            float w = W[(size_t)(n0 + n) * SSZ + k];
            __nv_bfloat16 wh, wl; split_bf(w, wh, wl);
            uint32_t o = (uint32_t)n * 2048u
                       + (uint32_t)(((k >> 3) ^ (n & 7)) << 4)
                       + (uint32_t)((k & 7) << 1);
            *(__nv_bfloat16*)(smem + base + o)       = wh;
            *(__nv_bfloat16*)(smem + base + WLO + o) = wl;
        }
    }
    {
        float* b1s = (float*)(smem + BIAS1);
        float* b2s = (float*)(smem + BIAS2);
        if (tid < NSL) { b1s[tid] = b1[n0 + tid]; b2s[tid] = b2[n0 + tid]; }
    }

    // ---- init S0 slice (cols n0..n0+16 of this mh half): [x0, zeros] ----
    // pair items: 128 rows x 8 col-pairs
    for (int idx = tid; idx < 128 * 8; idx += NTHR) {
        int row = idx >> 3, pc = idx & 7;
        int b = mh * 128 + row, k = n0 + 2 * pc;
        float v0 = (k < INSZ)     ? x[(size_t)b * INSZ + k]     : 0.0f;
        float v1 = (k + 1 < INSZ) ? x[(size_t)b * INSZ + k + 1] : 0.0f;
        *(float2*)&g_Sf[0][b][k] = make_float2(v0, v1);
        __nv_bfloat16 h0, l0, h1, l1;
        split_bf(v0, h0, l0); split_bf(v1, h1, l1);
        int mt = b >> 4, rr = b & 15;
        int lt  = (rr & 7) * 4 + (pc & 3);
        int reg = (rr >> 3) + 2 * (pc >> 2);
        g_SP[0][0][mt][k >> 4][lt * 4 + reg] = pk(h0, h1);
        g_SP[0][1][mt][k >> 4][lt * 4 + reg] = pk(l0, l1);
    }
    unsigned bc = 0;
    gbar(ep0, ++bc, cta);

    // ---- per-lane constants ----
    // A consumer: permuted fragment pointer (ktile base jg*16, lane*4 words)
    const int lane4 = lane * 4;
    // W consumer: n = (lane&7)+((lane>>4)&1)*8, k-half = (lane>>3)&1
    const uint32_t wn   = (uint32_t)((lane & 7) + ((lane >> 4) & 1) * 8);
    const uint32_t nx   = wn & 7u;
    const uint32_t wrow = wn * 2048u;
    const uint32_t c16b = (uint32_t)jg * 32u + (uint32_t)((lane >> 3) & 1);

    const int gr = lane >> 2;
    const int gc = 2 * (lane & 3);
    const float* b1s = (const float*)(smem + BIAS1);
    const float* b2s = (const float*)(smem + BIAS2);
    const float p = 0.97f;
    const float q = 1.0f - 0.97f;

    // epilogue permuted-store lane slot (jg==0 warps)
    const int ep_lt = gr * 4 + (lane & 3);     // (rr&7)*4 + ((c>>1)&3)

    for (int t = 0; t < SEQ; ++t) {
        const int cur = t & 1, nxt = (t + 1) & 1;

        // ============ Phase 1: H = |S @ W1^T + b1| ============
        {
            float acc0[4], acc1[4];
            mma_phase((const uint4*)&g_SP[cur][0][mtile][jg * 16][lane4],
                      (const uint4*)&g_SP[cur][1][mtile][jg * 16][lane4],
                      su + W1B + wrow, nx, c16b, acc0, acc1);
            kreduce(su, jg, m, lane, acc0, acc1);
            if (jg == 0) {
                uint32_t* hp = &g_HP[0][mtile][n0 >> 4][ep_lt * 4];
#pragma unroll
                for (int nt = 0; nt < 2; ++nt) {
                    const float* acc = nt ? acc1 : acc0;
                    int c = 8 * nt + gc;
#pragma unroll
                    for (int h = 0; h < 2; ++h) {
                        float v0 = fabsf(acc[2 * h]     + b1s[c]);
                        float v1 = fabsf(acc[2 * h + 1] + b1s[c + 1]);
                        __nv_bfloat16 h0, l0, h1, l1;
                        split_bf(v0, h0, l0); split_bf(v1, h1, l1);
                        hp[h + 2 * nt]              = pk(h0, h1);
                        hp[h + 2 * nt + 16 * 64 * 128] = pk(l0, l1);
                    }
                }
            }
        }
        gbar(ep0, ++bc, cta);

        // ============ Phase 2: S' = p*S + q*(H @ W2^T + b2) ============
        {
            float acc0[4], acc1[4];
            mma_phase((const uint4*)&g_HP[0][mtile][jg * 16][lane4],
                      (const uint4*)&g_HP[1][mtile][jg * 16][lane4],
                      su + W2B + wrow, nx, c16b, acc0, acc1);
            kreduce(su, jg, m, lane, acc0, acc1);
            if (jg == 0) {
                uint32_t* sph = &g_SP[nxt][0][mtile][(n0 + INSZ) >> 4][ep_lt * 4];
                uint32_t* spl = &g_SP[nxt][1][mtile][(n0 + INSZ) >> 4][ep_lt * 4];
#pragma unroll
                for (int nt = 0; nt < 2; ++nt) {
                    const float* acc = nt ? acc1 : acc0;
                    int c = 8 * nt + gc;
#pragma unroll
                    for (int h = 0; h < 2; ++h) {
                        int b = mh * 128 + 16 * m + gr + h * 8;
                        float2 sold = *(const float2*)&g_Sf[cur][b][n0 + c];
                        float n0v = p * sold.x + q * (acc[2 * h]     + b2s[c]);
                        float n1v = p * sold.y + q * (acc[2 * h + 1] + b2s[c + 1]);
                        if (n0 < SSZ - INSZ) {
                            *(float2*)&g_Sf[nxt][b][n0 + INSZ + c] = make_float2(n0v, n1v);
                            __nv_bfloat16 h0, l0, h1, l1;
                            split_bf(n0v, h0, l0); split_bf(n1v, h1, l1);
                            sph[h + 2 * nt] = pk(h0, h1);
                            spl[h + 2 * nt] = pk(l0, l1);
                        }
                        if (t == SEQ - 1 && n0 >= SSZ - OUTSZ) {
                            *(float2*)&out[(size_t)b * OUTSZ + (n0 - (SSZ - OUTSZ)) + c] =
                                make_float2(n0v, n1v);
                        }
                    }
                }
            }
            // inject x_{t+1} into cols [n0, n0+16) for n0 < 64 (jg==1 warps)
            if (n0 < INSZ && t + 1 < SEQ && jg == 1) {
                const float* xp = x + (size_t)(t + 1) * BATCH * INSZ;
                for (int idx = (tid & 255); idx < 128 * 8; idx += 256) {
                    int row = idx >> 3, pc = idx & 7;
                    int b = mh * 128 + row, k = n0 + 2 * pc;
                    float v0 = xp[(size_t)b * INSZ + k];
                    float v1 = xp[(size_t)b * INSZ + k + 1];
                    *(float2*)&g_Sf[nxt][b][k] = make_float2(v0, v1);
                    __nv_bfloat16 h0, l0, h1, l1;
                    split_bf(v0, h0, l0); split_bf(v1, h1, l1);
                    int mt = b >> 4, rr = b & 15;
                    int lt  = (rr & 7) * 4 + (pc & 3);
                    int reg = (rr >> 3) + 2 * (pc >> 2);
                    g_SP[nxt][0][mt][k >> 4][lt * 4 + reg] = pk(h0, h1);
                    g_SP[nxt][1][mt][k >> 4][lt * 4 + reg] = pk(l0, l1);
                }
            }
        }
        gbar(ep0, ++bc, cta);
    }
}

extern "C" void kernel_launch(void* const* d_in, const int* in_sizes, int n_in,
                              void* d_out, int out_size) {
    (void)in_sizes; (void)n_in; (void)out_size;
    const float* x  = (const float*)d_in[0];
    const float* W1 = (const float*)d_in[1];
    const float* b1 = (const float*)d_in[2];
    const float* W2 = (const float*)d_in[3];
    const float* b2 = (const float*)d_in[4];

    cudaFuncSetAttribute(resrnn_kernel,
                         cudaFuncAttributeMaxDynamicSharedMemorySize,
                         (int)SMEM_BYTES);
    resrnn_kernel<<<NCTA, NTHR, SMEM_BYTES>>>(x, W1, b1, W2, b2, (float*)d_out);
}